// round 4
// baseline (speedup 1.0000x reference)
#include <cuda_runtime.h>
#include <cuda_bf16.h>

#define D 128
#define HEADS 8
#define UNITS 16
#define MAX_NODES 50000
#define MAX_EDGES 800000

// Scratch (device globals: no allocation allowed)
__device__ float g_xp[MAX_NODES * D];       // projected features, 25.6 MB
__device__ float g_p[MAX_EDGES * HEADS];    // exp(score) per edge/head, 25.6 MB
__device__ float g_ssum[MAX_NODES * HEADS]; // softmax denominators

// ---------------------------------------------------------------------------
// Zero ssum and the output accumulator
// ---------------------------------------------------------------------------
__global__ void zero_kernel(float4* __restrict__ out4, int out_n4, int ssum_n4) {
    int i = blockIdx.x * blockDim.x + threadIdx.x;
    float4 z = make_float4(0.f, 0.f, 0.f, 0.f);
    if (i < out_n4) out4[i] = z;
    if (i < ssum_n4) reinterpret_cast<float4*>(g_ssum)[i] = z;
}

// ---------------------------------------------------------------------------
// GEMM: g_xp[n][j] = sum_k x[n][k] * W[k][j]   (W = kernel reshaped 128x128)
// Block: 128 threads (thread t owns output column t), 32 nodes per block.
// ---------------------------------------------------------------------------
__global__ void gemm_kernel(const float* __restrict__ x,
                            const float* __restrict__ W,
                            int n_nodes) {
    __shared__ float4 xs4[32 * 32]; // 32 nodes x 128 floats as float4
    const int t = threadIdx.x;      // 0..127 output column
    const int n0 = blockIdx.x * 32;
    const int nrows = min(32, n_nodes - n0);

    const float4* x4 = reinterpret_cast<const float4*>(x);
#pragma unroll
    for (int q = 0; q < 8; q++) {
        int idx = q * 128 + t;      // 0..1023
        int i = idx >> 5;           // node within tile
        int kq = idx & 31;          // float4 index in row
        xs4[idx] = (i < nrows) ? x4[(size_t)(n0 + i) * 32 + kq]
                               : make_float4(0.f, 0.f, 0.f, 0.f);
    }
    __syncthreads();

    float acc[32];
#pragma unroll
    for (int i = 0; i < 32; i++) acc[i] = 0.f;

    for (int kq = 0; kq < 32; kq++) {
        const float w0 = __ldg(&W[(4 * kq + 0) * D + t]);
        const float w1 = __ldg(&W[(4 * kq + 1) * D + t]);
        const float w2 = __ldg(&W[(4 * kq + 2) * D + t]);
        const float w3 = __ldg(&W[(4 * kq + 3) * D + t]);
#pragma unroll
        for (int i = 0; i < 32; i++) {
            float4 xv = xs4[i * 32 + kq]; // broadcast across block
            acc[i] = fmaf(xv.x, w0, acc[i]);
            acc[i] = fmaf(xv.y, w1, acc[i]);
            acc[i] = fmaf(xv.z, w2, acc[i]);
            acc[i] = fmaf(xv.w, w3, acc[i]);
        }
    }

    for (int i = 0; i < nrows; i++)
        g_xp[(size_t)(n0 + i) * D + t] = acc[i];
}

// ---------------------------------------------------------------------------
// Edge pass 1: per-edge per-head scores -> p = exp(score); ssum[tgt,h] += p
// One warp per edge; lane l handles 4 features (head = l/4).
// score[h] = sum_u leaky_relu(xp[t]+xp[s]+2*battn)[h,u] * ka1[h,u]
// (segment_max skipped: scores are O(1), exp cannot overflow; softmax is
//  shift-invariant up to the 1e-7 epsilon, effect << 1e-3 tolerance)
// ---------------------------------------------------------------------------
__global__ void edge_score_kernel(const int* __restrict__ edges,
                                  const float* __restrict__ ka1,
                                  const float* __restrict__ battn,
                                  int n_edges) {
    int gw = (blockIdx.x * blockDim.x + threadIdx.x) >> 5;
    int lane = threadIdx.x & 31;
    if (gw >= n_edges) return;

    const int src = edges[2 * gw];
    const int tgt = edges[2 * gw + 1];
    const int j = lane * 4;

    float4 xs = *reinterpret_cast<const float4*>(&g_xp[(size_t)src * D + j]);
    float4 xt = *reinterpret_cast<const float4*>(&g_xp[(size_t)tgt * D + j]);
    float4 kb = *reinterpret_cast<const float4*>(&battn[j]);
    float4 ka = *reinterpret_cast<const float4*>(&ka1[j]);

    float s0 = xs.x + xt.x + 2.f * kb.x; s0 = (s0 > 0.f) ? s0 : 0.2f * s0;
    float s1 = xs.y + xt.y + 2.f * kb.y; s1 = (s1 > 0.f) ? s1 : 0.2f * s1;
    float s2 = xs.z + xt.z + 2.f * kb.z; s2 = (s2 > 0.f) ? s2 : 0.2f * s2;
    float s3 = xs.w + xt.w + 2.f * kb.w; s3 = (s3 > 0.f) ? s3 : 0.2f * s3;

    float sum = fmaf(s0, ka.x, fmaf(s1, ka.y, fmaf(s2, ka.z, s3 * ka.w)));
    // reduce across the 4 lanes of this head
    sum += __shfl_xor_sync(0xFFFFFFFFu, sum, 1);
    sum += __shfl_xor_sync(0xFFFFFFFFu, sum, 2);

    if ((lane & 3) == 0) {
        int h = lane >> 2;
        float p = __expf(sum);
        g_p[(size_t)gw * HEADS + h] = p;
        atomicAdd(&g_ssum[(size_t)tgt * HEADS + h], p);
    }
}

// ---------------------------------------------------------------------------
// Edge pass 2: out[tgt] += (p / (ssum[tgt]+1e-7)) * xp[src]
// One warp per edge; vector RED (red.global.add.v4.f32) per lane.
// ---------------------------------------------------------------------------
__global__ void edge_aggr_kernel(const int* __restrict__ edges,
                                 float* __restrict__ out,
                                 int n_edges) {
    int gw = (blockIdx.x * blockDim.x + threadIdx.x) >> 5;
    int lane = threadIdx.x & 31;
    if (gw >= n_edges) return;

    const int src = edges[2 * gw];
    const int tgt = edges[2 * gw + 1];

    float w8 = 0.f;
    if (lane < HEADS) {
        float p = g_p[(size_t)gw * HEADS + lane];
        float s = g_ssum[(size_t)tgt * HEADS + lane];
        w8 = p / (s + 1e-7f);
    }
    const int h = lane >> 2;
    const float w = __shfl_sync(0xFFFFFFFFu, w8, h);

    const int j = lane * 4;
    float4 xv = *reinterpret_cast<const float4*>(&g_xp[(size_t)src * D + j]);
    float* dst = out + (size_t)tgt * D + j;
    asm volatile("red.global.add.v4.f32 [%0], {%1,%2,%3,%4};"
                 :: "l"(dst), "f"(w * xv.x), "f"(w * xv.y),
                    "f"(w * xv.z), "f"(w * xv.w)
                 : "memory");
}

// ---------------------------------------------------------------------------
// Epilogue: out = gelu_tanh(out + bias)
// ---------------------------------------------------------------------------
__device__ __forceinline__ float gelu_tanh(float v) {
    float c = 0.7978845608028654f * (v + 0.044715f * v * v * v);
    return 0.5f * v * (1.f + tanhf(c));
}

__global__ void gelu_kernel(float4* __restrict__ out4,
                            const float* __restrict__ bias,
                            int n4) {
    int i = blockIdx.x * blockDim.x + threadIdx.x;
    if (i >= n4) return;
    float4 v = out4[i];
    int j = (i * 4) & (D - 1);
    float4 b = *reinterpret_cast<const float4*>(&bias[j]);
    v.x = gelu_tanh(v.x + b.x);
    v.y = gelu_tanh(v.y + b.y);
    v.z = gelu_tanh(v.z + b.z);
    v.w = gelu_tanh(v.w + b.w);
    out4[i] = v;
}

// ---------------------------------------------------------------------------
extern "C" void kernel_launch(void* const* d_in, const int* in_sizes, int n_in,
                              void* d_out, int out_size) {
    const float* x     = (const float*)d_in[0];
    const int*   edges = (const int*)d_in[1];
    const float* W     = (const float*)d_in[2]; // (D, H, U) row-major == D x 128
    const float* ka1   = (const float*)d_in[3];
    const float* battn = (const float*)d_in[4];
    const float* bias  = (const float*)d_in[5];
    float* out = (float*)d_out;

    const int n_nodes = in_sizes[0] / D;
    const int n_edges = in_sizes[1] / 2;
    const int out_n4  = out_size / 4;
    const int ssum_n4 = (n_nodes * HEADS) / 4;

    // 1. zero accumulators
    {
        int n = max(out_n4, ssum_n4);
        zero_kernel<<<(n + 255) / 256, 256>>>((float4*)out, out_n4, ssum_n4);
    }
    // 2. projection GEMM
    gemm_kernel<<<(n_nodes + 31) / 32, 128>>>(x, W, n_nodes);
    // 3. scores + softmax denominators
    {
        int warps = n_edges;
        int blocks = (warps * 32 + 255) / 256;
        edge_score_kernel<<<blocks, 256>>>(edges, ka1, battn, n_edges);
    }
    // 4. weighted aggregation
    {
        int warps = n_edges;
        int blocks = (warps * 32 + 255) / 256;
        edge_aggr_kernel<<<blocks, 256>>>(edges, out, n_edges);
    }
    // 5. bias + gelu
    gelu_kernel<<<(out_n4 + 255) / 256, 256>>>((float4*)out, bias, out_n4);
}

// round 5
// speedup vs baseline: 1.2813x; 1.2813x over previous
#include <cuda_runtime.h>
#include <cuda_bf16.h>

#define D 128
#define HEADS 8
#define UNITS 16
#define MAX_NODES 50000
#define MAX_EDGES 800000

typedef unsigned long long ull;

// Scratch (device globals: no allocation allowed)
__device__ float g_xp[MAX_NODES * D];        // projected features, 25.6 MB
__device__ int   g_deg[MAX_NODES];           // in-degree histogram
__device__ int   g_rowptr[MAX_NODES + 1];    // CSR row pointers (by target)
__device__ int   g_cursor[MAX_NODES];        // scatter cursors
__device__ int   g_csrc[MAX_EDGES];          // CSR: source node per slot

// ---------------------------------------------------------------------------
// 1. zero the degree histogram
// ---------------------------------------------------------------------------
__global__ void init_deg_kernel(int n_nodes) {
    int i = blockIdx.x * blockDim.x + threadIdx.x;
    if (i < n_nodes) g_deg[i] = 0;
}

// ---------------------------------------------------------------------------
// 2. GEMM: g_xp[n][j] = sum_k x[n][k] * W[k][j]  using packed fma.rn.f32x2
//    (pack along K: x pairs are contiguous -> come free out of LDS.128;
//     weight pairs packed once per kq, amortized over 32 nodes)
// ---------------------------------------------------------------------------
__global__ void gemm_kernel(const float* __restrict__ x,
                            const float* __restrict__ W,
                            int n_nodes) {
    __shared__ ulonglong2 xs[32 * 32];  // 32 nodes x 128 floats, as 2x f32x2
    const int t = threadIdx.x;          // 0..127 output column
    const int n0 = blockIdx.x * 32;
    const int nrows = min(32, n_nodes - n0);

    const float4* x4 = reinterpret_cast<const float4*>(x);
#pragma unroll
    for (int q = 0; q < 8; q++) {
        int idx = q * 128 + t;
        int i = idx >> 5;
        int kq = idx & 31;
        float4 v = (i < nrows) ? x4[(size_t)(n0 + i) * 32 + kq]
                               : make_float4(0.f, 0.f, 0.f, 0.f);
        xs[idx] = *reinterpret_cast<ulonglong2*>(&v);
    }
    __syncthreads();

    ull acc2[32];
#pragma unroll
    for (int i = 0; i < 32; i++) acc2[i] = 0ull;  // {+0.f, +0.f}

    for (int kq = 0; kq < 32; kq++) {
        const float w0 = W[(4 * kq + 0) * D + t];
        const float w1 = W[(4 * kq + 1) * D + t];
        const float w2 = W[(4 * kq + 2) * D + t];
        const float w3 = W[(4 * kq + 3) * D + t];
        ull wp0, wp1;
        asm("mov.b64 %0, {%1,%2};" : "=l"(wp0) : "f"(w0), "f"(w1));
        asm("mov.b64 %0, {%1,%2};" : "=l"(wp1) : "f"(w2), "f"(w3));
#pragma unroll
        for (int i = 0; i < 32; i++) {
            ulonglong2 xv = xs[i * 32 + kq];  // broadcast across block
            asm("fma.rn.f32x2 %0, %1, %2, %0;" : "+l"(acc2[i]) : "l"(xv.x), "l"(wp0));
            asm("fma.rn.f32x2 %0, %1, %2, %0;" : "+l"(acc2[i]) : "l"(xv.y), "l"(wp1));
        }
    }

    for (int i = 0; i < nrows; i++) {
        float lo, hi;
        asm("mov.b64 {%0,%1}, %2;" : "=f"(lo), "=f"(hi) : "l"(acc2[i]));
        g_xp[(size_t)(n0 + i) * D + t] = lo + hi;
    }
}

// ---------------------------------------------------------------------------
// 3. histogram of targets
// ---------------------------------------------------------------------------
__global__ void hist_kernel(const int* __restrict__ edges, int n_edges) {
    int e = blockIdx.x * blockDim.x + threadIdx.x;
    if (e >= n_edges) return;
    atomicAdd(&g_deg[edges[2 * e + 1]], 1);
}

// ---------------------------------------------------------------------------
// 4. exclusive scan -> rowptr + cursor  (single block, chunked Hillis-Steele)
// ---------------------------------------------------------------------------
__global__ void scan_kernel(int n_nodes) {
    __shared__ int sh[1024];
    __shared__ int s_carry;
    const int tid = threadIdx.x;
    if (tid == 0) s_carry = 0;
    __syncthreads();

    const int nchunks = (n_nodes + 1023) >> 10;
    for (int ch = 0; ch < nchunks; ch++) {
        int i = (ch << 10) + tid;
        int v = (i < n_nodes) ? g_deg[i] : 0;
        sh[tid] = v;
        __syncthreads();
        int xacc = v;
        for (int off = 1; off < 1024; off <<= 1) {
            int tmp = (tid >= off) ? sh[tid - off] : 0;
            __syncthreads();
            xacc += tmp;
            sh[tid] = xacc;
            __syncthreads();
        }
        int base = s_carry;
        if (i < n_nodes) {
            int excl = base + xacc - v;
            g_rowptr[i] = excl;
            g_cursor[i] = excl;
        }
        int tot = sh[1023];
        __syncthreads();
        if (tid == 0) s_carry = base + tot;
        __syncthreads();
    }
    if (tid == 0) g_rowptr[n_nodes] = s_carry;
}

// ---------------------------------------------------------------------------
// 5. scatter sources into CSR slots
// ---------------------------------------------------------------------------
__global__ void scatter_kernel(const int* __restrict__ edges, int n_edges) {
    int e = blockIdx.x * blockDim.x + threadIdx.x;
    if (e >= n_edges) return;
    int src = edges[2 * e];
    int tgt = edges[2 * e + 1];
    int pos = atomicAdd(&g_cursor[tgt], 1);
    g_csrc[pos] = src;
}

// ---------------------------------------------------------------------------
// 6. fused attention: one warp per target node, single pass over its edges.
//    out[tgt] = gelu( (sum_e p_e * xp[src_e]) / (sum_e p_e + 1e-7) + bias )
//    (normalization denominator is per-target-constant, so no second pass;
//     segment_max skipped: scores are O(1), exp cannot overflow; effect on
//     the 1e-7 epsilon term is << 1e-3 tolerance)
// ---------------------------------------------------------------------------
__device__ __forceinline__ float gelu_tanh(float v) {
    float c = 0.7978845608028654f * (v + 0.044715f * v * v * v);
    return 0.5f * v * (1.f + tanhf(c));
}

__global__ void attn_kernel(const float* __restrict__ ka1,
                            const float* __restrict__ battn,
                            const float* __restrict__ bias,
                            float* __restrict__ out,
                            int n_nodes) {
    int w = (blockIdx.x * blockDim.x + threadIdx.x) >> 5;
    if (w >= n_nodes) return;
    const int lane = threadIdx.x & 31;
    const int j = lane * 4;

    const int row = g_rowptr[w];
    const int end = g_rowptr[w + 1];

    const float4 xt = *reinterpret_cast<const float4*>(&g_xp[(size_t)w * D + j]);
    const float4 kb = *reinterpret_cast<const float4*>(&battn[j]);
    const float4 ka = *reinterpret_cast<const float4*>(&ka1[j]);

    const float tb0 = xt.x + 2.f * kb.x;
    const float tb1 = xt.y + 2.f * kb.y;
    const float tb2 = xt.z + 2.f * kb.z;
    const float tb3 = xt.w + 2.f * kb.w;

    float a0 = 0.f, a1 = 0.f, a2 = 0.f, a3 = 0.f, ssum = 0.f;

    for (int e = row; e < end; e++) {
        int src = __ldg(&g_csrc[e]);
        float4 xv = *reinterpret_cast<const float4*>(&g_xp[(size_t)src * D + j]);

        float s0 = xv.x + tb0; s0 = (s0 > 0.f) ? s0 : 0.2f * s0;
        float s1 = xv.y + tb1; s1 = (s1 > 0.f) ? s1 : 0.2f * s1;
        float s2 = xv.z + tb2; s2 = (s2 > 0.f) ? s2 : 0.2f * s2;
        float s3 = xv.w + tb3; s3 = (s3 > 0.f) ? s3 : 0.2f * s3;

        float part = fmaf(s0, ka.x, fmaf(s1, ka.y, fmaf(s2, ka.z, s3 * ka.w)));
        part += __shfl_xor_sync(0xFFFFFFFFu, part, 1);
        part += __shfl_xor_sync(0xFFFFFFFFu, part, 2);

        float p = __expf(part);
        ssum += p;
        a0 = fmaf(p, xv.x, a0);
        a1 = fmaf(p, xv.y, a1);
        a2 = fmaf(p, xv.z, a2);
        a3 = fmaf(p, xv.w, a3);
    }

    const float inv = 1.f / (ssum + 1e-7f);
    const float4 b = *reinterpret_cast<const float4*>(&bias[j]);
    float4 o;
    o.x = gelu_tanh(fmaf(a0, inv, b.x));
    o.y = gelu_tanh(fmaf(a1, inv, b.y));
    o.z = gelu_tanh(fmaf(a2, inv, b.z));
    o.w = gelu_tanh(fmaf(a3, inv, b.w));
    *reinterpret_cast<float4*>(&out[(size_t)w * D + j]) = o;
}

// ---------------------------------------------------------------------------
extern "C" void kernel_launch(void* const* d_in, const int* in_sizes, int n_in,
                              void* d_out, int out_size) {
    const float* x     = (const float*)d_in[0];
    const int*   edges = (const int*)d_in[1];
    const float* W     = (const float*)d_in[2]; // (D, H, U) row-major == D x 128
    const float* ka1   = (const float*)d_in[3];
    const float* battn = (const float*)d_in[4];
    const float* bias  = (const float*)d_in[5];
    float* out = (float*)d_out;

    const int n_nodes = in_sizes[0] / D;
    const int n_edges = in_sizes[1] / 2;

    // 1. zero degree histogram
    init_deg_kernel<<<(n_nodes + 255) / 256, 256>>>(n_nodes);
    // 2. projection GEMM (f32x2 packed)
    gemm_kernel<<<(n_nodes + 31) / 32, 128>>>(x, W, n_nodes);
    // 3. in-degree histogram
    hist_kernel<<<(n_edges + 255) / 256, 256>>>(edges, n_edges);
    // 4. scan -> rowptr/cursor
    scan_kernel<<<1, 1024>>>(n_nodes);
    // 5. scatter sources into CSR
    scatter_kernel<<<(n_edges + 255) / 256, 256>>>(edges, n_edges);
    // 6. fused per-node attention (score + softmax + aggregate + bias + gelu)
    {
        int threads = 256;
        int blocks = (n_nodes * 32 + threads - 1) / threads;
        attn_kernel<<<blocks, threads>>>(ka1, battn, bias, out, n_nodes);
    }
}

// round 6
// speedup vs baseline: 1.7257x; 1.3469x over previous
#include <cuda_runtime.h>
#include <cuda_bf16.h>

#define D 128
#define HEADS 8
#define UNITS 16
#define MAX_NODES 50000
#define MAX_EDGES 800000
#define SCAN_BLK 1024
#define MAX_SCAN_BLOCKS ((MAX_NODES + SCAN_BLK - 1) / SCAN_BLK)

typedef unsigned long long ull;

// Scratch (device globals: no allocation allowed)
__device__ float g_xp[MAX_NODES * D];        // projected features, 25.6 MB
__device__ int   g_deg[MAX_NODES];           // in-degree histogram
__device__ int   g_rowptr[MAX_NODES + 1];    // CSR row pointers (by target)
__device__ int   g_cursor[MAX_NODES];        // scatter cursors
__device__ int   g_csrc[MAX_EDGES];          // CSR: source node per slot
__device__ int   g_blocksum[MAX_SCAN_BLOCKS];
__device__ int   g_blockoff[MAX_SCAN_BLOCKS];

// ---------------------------------------------------------------------------
// 1. zero the degree histogram
// ---------------------------------------------------------------------------
__global__ void init_deg_kernel(int n_nodes) {
    int i = blockIdx.x * blockDim.x + threadIdx.x;
    if (i < n_nodes) g_deg[i] = 0;
}

// ---------------------------------------------------------------------------
// 2. GEMM: g_xp[n][j] = sum_k x[n][k] * W[k][j]  using packed fma.rn.f32x2
// ---------------------------------------------------------------------------
__global__ void gemm_kernel(const float* __restrict__ x,
                            const float* __restrict__ W,
                            int n_nodes) {
    __shared__ ulonglong2 xs[32 * 32];  // 32 nodes x 128 floats, as 2x f32x2
    const int t = threadIdx.x;          // 0..127 output column
    const int n0 = blockIdx.x * 32;
    const int nrows = min(32, n_nodes - n0);

    const float4* x4 = reinterpret_cast<const float4*>(x);
#pragma unroll
    for (int q = 0; q < 8; q++) {
        int idx = q * 128 + t;
        int i = idx >> 5;
        int kq = idx & 31;
        float4 v = (i < nrows) ? x4[(size_t)(n0 + i) * 32 + kq]
                               : make_float4(0.f, 0.f, 0.f, 0.f);
        xs[idx] = *reinterpret_cast<ulonglong2*>(&v);
    }
    __syncthreads();

    ull acc2[32];
#pragma unroll
    for (int i = 0; i < 32; i++) acc2[i] = 0ull;  // {+0.f, +0.f}

    for (int kq = 0; kq < 32; kq++) {
        const float w0 = W[(4 * kq + 0) * D + t];
        const float w1 = W[(4 * kq + 1) * D + t];
        const float w2 = W[(4 * kq + 2) * D + t];
        const float w3 = W[(4 * kq + 3) * D + t];
        ull wp0, wp1;
        asm("mov.b64 %0, {%1,%2};" : "=l"(wp0) : "f"(w0), "f"(w1));
        asm("mov.b64 %0, {%1,%2};" : "=l"(wp1) : "f"(w2), "f"(w3));
#pragma unroll
        for (int i = 0; i < 32; i++) {
            ulonglong2 xv = xs[i * 32 + kq];  // broadcast across block
            asm("fma.rn.f32x2 %0, %1, %2, %0;" : "+l"(acc2[i]) : "l"(xv.x), "l"(wp0));
            asm("fma.rn.f32x2 %0, %1, %2, %0;" : "+l"(acc2[i]) : "l"(xv.y), "l"(wp1));
        }
    }

    for (int i = 0; i < nrows; i++) {
        float lo, hi;
        asm("mov.b64 {%0,%1}, %2;" : "=f"(lo), "=f"(hi) : "l"(acc2[i]));
        g_xp[(size_t)(n0 + i) * D + t] = lo + hi;
    }
}

// ---------------------------------------------------------------------------
// 3. histogram of targets
// ---------------------------------------------------------------------------
__global__ void hist_kernel(const int* __restrict__ edges, int n_edges) {
    int e = blockIdx.x * blockDim.x + threadIdx.x;
    if (e >= n_edges) return;
    atomicAdd(&g_deg[edges[2 * e + 1]], 1);
}

// ---------------------------------------------------------------------------
// 4a. per-block scan: warp-shuffle inclusive scan + cross-warp combine.
//     Writes exclusive partials into g_rowptr and per-block totals.
// ---------------------------------------------------------------------------
__global__ void scan_local_kernel(int n_nodes) {
    __shared__ int wsum[32];
    const int tid = threadIdx.x;
    const int lane = tid & 31;
    const int warp = tid >> 5;
    const int i = blockIdx.x * SCAN_BLK + tid;

    int v = (i < n_nodes) ? g_deg[i] : 0;
    int incl = v;
#pragma unroll
    for (int off = 1; off < 32; off <<= 1) {
        int t = __shfl_up_sync(0xFFFFFFFFu, incl, off);
        if (lane >= off) incl += t;
    }
    if (lane == 31) wsum[warp] = incl;
    __syncthreads();
    if (warp == 0) {
        int wv = wsum[lane];
        int winc = wv;
#pragma unroll
        for (int off = 1; off < 32; off <<= 1) {
            int t = __shfl_up_sync(0xFFFFFFFFu, winc, off);
            if (lane >= off) winc += t;
        }
        wsum[lane] = winc - wv;  // exclusive warp offsets
        if (lane == 31) g_blocksum[blockIdx.x] = winc;
    }
    __syncthreads();

    if (i < n_nodes) g_rowptr[i] = incl - v + wsum[warp];  // exclusive partial
}

// ---------------------------------------------------------------------------
// 4b. scan of block sums (single warp, sequential carry over 32-chunks)
// ---------------------------------------------------------------------------
__global__ void scan_blocksum_kernel(int nb) {
    const int lane = threadIdx.x;
    int carry = 0;
    for (int base = 0; base < nb; base += 32) {
        int i = base + lane;
        int v = (i < nb) ? g_blocksum[i] : 0;
        int incl = v;
#pragma unroll
        for (int off = 1; off < 32; off <<= 1) {
            int t = __shfl_up_sync(0xFFFFFFFFu, incl, off);
            if (lane >= off) incl += t;
        }
        if (i < nb) g_blockoff[i] = carry + incl - v;
        carry += __shfl_sync(0xFFFFFFFFu, incl, 31);
    }
}

// ---------------------------------------------------------------------------
// 4c. finalize: add block offsets, fill rowptr + cursor, cap rowptr[n]
// ---------------------------------------------------------------------------
__global__ void scan_finalize_kernel(int n_nodes, int n_edges) {
    int i = blockIdx.x * SCAN_BLK + threadIdx.x;
    if (i < n_nodes) {
        int r = g_rowptr[i] + g_blockoff[blockIdx.x];
        g_rowptr[i] = r;
        g_cursor[i] = r;
    }
    if (i == 0) g_rowptr[n_nodes] = n_edges;
}

// ---------------------------------------------------------------------------
// 5. scatter sources into CSR slots
// ---------------------------------------------------------------------------
__global__ void scatter_kernel(const int* __restrict__ edges, int n_edges) {
    int e = blockIdx.x * blockDim.x + threadIdx.x;
    if (e >= n_edges) return;
    int src = edges[2 * e];
    int tgt = edges[2 * e + 1];
    int pos = atomicAdd(&g_cursor[tgt], 1);
    g_csrc[pos] = src;
}

// ---------------------------------------------------------------------------
// 6. fused attention: one warp per target node, single pass over its edges.
//    out[tgt] = gelu( (sum_e p_e * xp[src_e]) / (sum_e p_e + 1e-7) + bias )
// ---------------------------------------------------------------------------
__device__ __forceinline__ float gelu_tanh(float v) {
    float c = 0.7978845608028654f * (v + 0.044715f * v * v * v);
    return 0.5f * v * (1.f + tanhf(c));
}

__global__ void attn_kernel(const float* __restrict__ ka1,
                            const float* __restrict__ battn,
                            const float* __restrict__ bias,
                            float* __restrict__ out,
                            int n_nodes) {
    int w = (blockIdx.x * blockDim.x + threadIdx.x) >> 5;
    if (w >= n_nodes) return;
    const int lane = threadIdx.x & 31;
    const int j = lane * 4;

    const int row = g_rowptr[w];
    const int end = g_rowptr[w + 1];

    const float4 xt = *reinterpret_cast<const float4*>(&g_xp[(size_t)w * D + j]);
    const float4 kb = *reinterpret_cast<const float4*>(&battn[j]);
    const float4 ka = *reinterpret_cast<const float4*>(&ka1[j]);

    const float tb0 = xt.x + 2.f * kb.x;
    const float tb1 = xt.y + 2.f * kb.y;
    const float tb2 = xt.z + 2.f * kb.z;
    const float tb3 = xt.w + 2.f * kb.w;

    float a0 = 0.f, a1 = 0.f, a2 = 0.f, a3 = 0.f, ssum = 0.f;

    for (int e = row; e < end; e++) {
        int src = __ldg(&g_csrc[e]);
        float4 xv = *reinterpret_cast<const float4*>(&g_xp[(size_t)src * D + j]);

        float s0 = xv.x + tb0; s0 = (s0 > 0.f) ? s0 : 0.2f * s0;
        float s1 = xv.y + tb1; s1 = (s1 > 0.f) ? s1 : 0.2f * s1;
        float s2 = xv.z + tb2; s2 = (s2 > 0.f) ? s2 : 0.2f * s2;
        float s3 = xv.w + tb3; s3 = (s3 > 0.f) ? s3 : 0.2f * s3;

        float part = fmaf(s0, ka.x, fmaf(s1, ka.y, fmaf(s2, ka.z, s3 * ka.w)));
        part += __shfl_xor_sync(0xFFFFFFFFu, part, 1);
        part += __shfl_xor_sync(0xFFFFFFFFu, part, 2);

        float p = __expf(part);
        ssum += p;
        a0 = fmaf(p, xv.x, a0);
        a1 = fmaf(p, xv.y, a1);
        a2 = fmaf(p, xv.z, a2);
        a3 = fmaf(p, xv.w, a3);
    }

    const float inv = 1.f / (ssum + 1e-7f);
    const float4 b = *reinterpret_cast<const float4*>(&bias[j]);
    float4 o;
    o.x = gelu_tanh(fmaf(a0, inv, b.x));
    o.y = gelu_tanh(fmaf(a1, inv, b.y));
    o.z = gelu_tanh(fmaf(a2, inv, b.z));
    o.w = gelu_tanh(fmaf(a3, inv, b.w));
    *reinterpret_cast<float4*>(&out[(size_t)w * D + j]) = o;
}

// ---------------------------------------------------------------------------
extern "C" void kernel_launch(void* const* d_in, const int* in_sizes, int n_in,
                              void* d_out, int out_size) {
    const float* x     = (const float*)d_in[0];
    const int*   edges = (const int*)d_in[1];
    const float* W     = (const float*)d_in[2]; // (D, H, U) row-major == D x 128
    const float* ka1   = (const float*)d_in[3];
    const float* battn = (const float*)d_in[4];
    const float* bias  = (const float*)d_in[5];
    float* out = (float*)d_out;

    const int n_nodes = in_sizes[0] / D;
    const int n_edges = in_sizes[1] / 2;
    const int nb = (n_nodes + SCAN_BLK - 1) / SCAN_BLK;

    // 1. zero degree histogram
    init_deg_kernel<<<(n_nodes + 255) / 256, 256>>>(n_nodes);
    // 2. projection GEMM (f32x2 packed)
    gemm_kernel<<<(n_nodes + 31) / 32, 128>>>(x, W, n_nodes);
    // 3. in-degree histogram
    hist_kernel<<<(n_edges + 255) / 256, 256>>>(edges, n_edges);
    // 4. multi-block exclusive scan -> rowptr/cursor
    scan_local_kernel<<<nb, SCAN_BLK>>>(n_nodes);
    scan_blocksum_kernel<<<1, 32>>>(nb);
    scan_finalize_kernel<<<nb, SCAN_BLK>>>(n_nodes, n_edges);
    // 5. scatter sources into CSR
    scatter_kernel<<<(n_edges + 255) / 256, 256>>>(edges, n_edges);
    // 6. fused per-node attention (score + softmax + aggregate + bias + gelu)
    {
        int threads = 256;
        int blocks = (n_nodes * 32 + threads - 1) / threads;
        attn_kernel<<<blocks, threads>>>(ka1, battn, bias, out, n_nodes);
    }
}

// round 7
// speedup vs baseline: 1.8463x; 1.0698x over previous
#include <cuda_runtime.h>
#include <cuda_bf16.h>

#define D 128
#define HEADS 8
#define UNITS 16
#define MAX_NODES 50000
#define MAX_EDGES 800000
#define SCAN_BLK 1024
#define MAX_SCAN_BLOCKS ((MAX_NODES + SCAN_BLK - 1) / SCAN_BLK)

typedef unsigned long long ull;

// Scratch (device globals: no allocation allowed)
__device__ float g_xp[MAX_NODES * D];        // projected features, 25.6 MB
__device__ int   g_deg[MAX_NODES];           // in-degree histogram
__device__ int   g_rowptr[MAX_NODES + 1];    // CSR row pointers (by target)
__device__ int   g_cursor[MAX_NODES];        // scatter cursors
__device__ int   g_csrc[MAX_EDGES];          // CSR: source node per slot
__device__ int   g_blocksum[MAX_SCAN_BLOCKS];
__device__ int   g_blockoff[MAX_SCAN_BLOCKS];

// ---------------------------------------------------------------------------
// 1. zero the degree histogram
// ---------------------------------------------------------------------------
__global__ void init_deg_kernel(int n_nodes) {
    int i = blockIdx.x * blockDim.x + threadIdx.x;
    if (i < n_nodes) g_deg[i] = 0;
}

// ---------------------------------------------------------------------------
// 2. GEMM: g_xp[n][j] = sum_k x[n][k] * W[k][j]  using packed fma.rn.f32x2
// ---------------------------------------------------------------------------
__global__ void gemm_kernel(const float* __restrict__ x,
                            const float* __restrict__ W,
                            int n_nodes) {
    __shared__ ulonglong2 xs[32 * 32];  // 32 nodes x 128 floats, as 2x f32x2
    const int t = threadIdx.x;          // 0..127 output column
    const int n0 = blockIdx.x * 32;
    const int nrows = min(32, n_nodes - n0);

    const float4* x4 = reinterpret_cast<const float4*>(x);
#pragma unroll
    for (int q = 0; q < 8; q++) {
        int idx = q * 128 + t;
        int i = idx >> 5;
        int kq = idx & 31;
        float4 v = (i < nrows) ? x4[(size_t)(n0 + i) * 32 + kq]
                               : make_float4(0.f, 0.f, 0.f, 0.f);
        xs[idx] = *reinterpret_cast<ulonglong2*>(&v);
    }
    __syncthreads();

    ull acc2[32];
#pragma unroll
    for (int i = 0; i < 32; i++) acc2[i] = 0ull;  // {+0.f, +0.f}

    for (int kq = 0; kq < 32; kq++) {
        const float w0 = W[(4 * kq + 0) * D + t];
        const float w1 = W[(4 * kq + 1) * D + t];
        const float w2 = W[(4 * kq + 2) * D + t];
        const float w3 = W[(4 * kq + 3) * D + t];
        ull wp0, wp1;
        asm("mov.b64 %0, {%1,%2};" : "=l"(wp0) : "f"(w0), "f"(w1));
        asm("mov.b64 %0, {%1,%2};" : "=l"(wp1) : "f"(w2), "f"(w3));
#pragma unroll
        for (int i = 0; i < 32; i++) {
            ulonglong2 xv = xs[i * 32 + kq];  // broadcast across block
            asm("fma.rn.f32x2 %0, %1, %2, %0;" : "+l"(acc2[i]) : "l"(xv.x), "l"(wp0));
            asm("fma.rn.f32x2 %0, %1, %2, %0;" : "+l"(acc2[i]) : "l"(xv.y), "l"(wp1));
        }
    }

    for (int i = 0; i < nrows; i++) {
        float lo, hi;
        asm("mov.b64 {%0,%1}, %2;" : "=f"(lo), "=f"(hi) : "l"(acc2[i]));
        g_xp[(size_t)(n0 + i) * D + t] = lo + hi;
    }
}

// ---------------------------------------------------------------------------
// 3. histogram of targets (int2 edge load)
// ---------------------------------------------------------------------------
__global__ void hist_kernel(const int2* __restrict__ edges, int n_edges) {
    int e = blockIdx.x * blockDim.x + threadIdx.x;
    if (e >= n_edges) return;
    atomicAdd(&g_deg[edges[e].y], 1);
}

// ---------------------------------------------------------------------------
// 4a. per-block scan: warp-shuffle inclusive scan + cross-warp combine.
// ---------------------------------------------------------------------------
__global__ void scan_local_kernel(int n_nodes) {
    __shared__ int wsum[32];
    const int tid = threadIdx.x;
    const int lane = tid & 31;
    const int warp = tid >> 5;
    const int i = blockIdx.x * SCAN_BLK + tid;

    int v = (i < n_nodes) ? g_deg[i] : 0;
    int incl = v;
#pragma unroll
    for (int off = 1; off < 32; off <<= 1) {
        int t = __shfl_up_sync(0xFFFFFFFFu, incl, off);
        if (lane >= off) incl += t;
    }
    if (lane == 31) wsum[warp] = incl;
    __syncthreads();
    if (warp == 0) {
        int wv = wsum[lane];
        int winc = wv;
#pragma unroll
        for (int off = 1; off < 32; off <<= 1) {
            int t = __shfl_up_sync(0xFFFFFFFFu, winc, off);
            if (lane >= off) winc += t;
        }
        wsum[lane] = winc - wv;  // exclusive warp offsets
        if (lane == 31) g_blocksum[blockIdx.x] = winc;
    }
    __syncthreads();

    if (i < n_nodes) g_rowptr[i] = incl - v + wsum[warp];  // exclusive partial
}

// ---------------------------------------------------------------------------
// 4b. scan of block sums (single warp)
// ---------------------------------------------------------------------------
__global__ void scan_blocksum_kernel(int nb) {
    const int lane = threadIdx.x;
    int carry = 0;
    for (int base = 0; base < nb; base += 32) {
        int i = base + lane;
        int v = (i < nb) ? g_blocksum[i] : 0;
        int incl = v;
#pragma unroll
        for (int off = 1; off < 32; off <<= 1) {
            int t = __shfl_up_sync(0xFFFFFFFFu, incl, off);
            if (lane >= off) incl += t;
        }
        if (i < nb) g_blockoff[i] = carry + incl - v;
        carry += __shfl_sync(0xFFFFFFFFu, incl, 31);
    }
}

// ---------------------------------------------------------------------------
// 4c. finalize: add block offsets, fill rowptr + cursor, cap rowptr[n]
// ---------------------------------------------------------------------------
__global__ void scan_finalize_kernel(int n_nodes, int n_edges) {
    int i = blockIdx.x * SCAN_BLK + threadIdx.x;
    if (i < n_nodes) {
        int r = g_rowptr[i] + g_blockoff[blockIdx.x];
        g_rowptr[i] = r;
        g_cursor[i] = r;
    }
    if (i == 0) g_rowptr[n_nodes] = n_edges;
}

// ---------------------------------------------------------------------------
// 5. scatter sources into CSR slots (int2 edge load)
// ---------------------------------------------------------------------------
__global__ void scatter_kernel(const int2* __restrict__ edges, int n_edges) {
    int e = blockIdx.x * blockDim.x + threadIdx.x;
    if (e >= n_edges) return;
    int2 ed = edges[e];
    int pos = atomicAdd(&g_cursor[ed.y], 1);
    g_csrc[pos] = ed.x;
}

// ---------------------------------------------------------------------------
// 6. fused attention: one warp per target node, software-pipelined (MLP=4).
//    out[tgt] = gelu( (sum_e p_e * xp[src_e]) / (sum_e p_e + 1e-7) + bias )
// ---------------------------------------------------------------------------
__device__ __forceinline__ float gelu_tanh(float v) {
    float c = 0.7978845608028654f * (v + 0.044715f * v * v * v);
    return 0.5f * v * (1.f + tanhf(c));
}

__global__ void attn_kernel(const float* __restrict__ ka1,
                            const float* __restrict__ battn,
                            const float* __restrict__ bias,
                            float* __restrict__ out,
                            int n_nodes) {
    int w = (blockIdx.x * blockDim.x + threadIdx.x) >> 5;
    if (w >= n_nodes) return;
    const int lane = threadIdx.x & 31;
    const int j = lane * 4;

    const int row = g_rowptr[w];
    const int end = g_rowptr[w + 1];

    const float4 xt = *reinterpret_cast<const float4*>(&g_xp[(size_t)w * D + j]);
    const float4 kb = *reinterpret_cast<const float4*>(&battn[j]);
    const float4 ka = *reinterpret_cast<const float4*>(&ka1[j]);

    const float tb0 = xt.x + 2.f * kb.x;
    const float tb1 = xt.y + 2.f * kb.y;
    const float tb2 = xt.z + 2.f * kb.z;
    const float tb3 = xt.w + 2.f * kb.w;

    float a0 = 0.f, a1 = 0.f, a2 = 0.f, a3 = 0.f, ssum = 0.f;

    // body shared by pipelined + tail paths
    auto process = [&](float4 xv) {
        float s0 = xv.x + tb0; s0 = (s0 > 0.f) ? s0 : 0.2f * s0;
        float s1 = xv.y + tb1; s1 = (s1 > 0.f) ? s1 : 0.2f * s1;
        float s2 = xv.z + tb2; s2 = (s2 > 0.f) ? s2 : 0.2f * s2;
        float s3 = xv.w + tb3; s3 = (s3 > 0.f) ? s3 : 0.2f * s3;
        float part = fmaf(s0, ka.x, fmaf(s1, ka.y, fmaf(s2, ka.z, s3 * ka.w)));
        part += __shfl_xor_sync(0xFFFFFFFFu, part, 1);
        part += __shfl_xor_sync(0xFFFFFFFFu, part, 2);
        float p = __expf(part);
        ssum += p;
        a0 = fmaf(p, xv.x, a0);
        a1 = fmaf(p, xv.y, a1);
        a2 = fmaf(p, xv.z, a2);
        a3 = fmaf(p, xv.w, a3);
    };

    int e = row;
    // pipelined main loop: batch 4 indices, issue 4 independent gathers
    for (; e + 4 <= end; e += 4) {
        int s0i = __ldg(&g_csrc[e + 0]);
        int s1i = __ldg(&g_csrc[e + 1]);
        int s2i = __ldg(&g_csrc[e + 2]);
        int s3i = __ldg(&g_csrc[e + 3]);
        float4 v0 = *reinterpret_cast<const float4*>(&g_xp[(size_t)s0i * D + j]);
        float4 v1 = *reinterpret_cast<const float4*>(&g_xp[(size_t)s1i * D + j]);
        float4 v2 = *reinterpret_cast<const float4*>(&g_xp[(size_t)s2i * D + j]);
        float4 v3 = *reinterpret_cast<const float4*>(&g_xp[(size_t)s3i * D + j]);
        process(v0);
        process(v1);
        process(v2);
        process(v3);
    }
    // tail
    for (; e < end; e++) {
        int si = __ldg(&g_csrc[e]);
        float4 v = *reinterpret_cast<const float4*>(&g_xp[(size_t)si * D + j]);
        process(v);
    }

    const float inv = 1.f / (ssum + 1e-7f);
    const float4 b = *reinterpret_cast<const float4*>(&bias[j]);
    float4 o;
    o.x = gelu_tanh(fmaf(a0, inv, b.x));
    o.y = gelu_tanh(fmaf(a1, inv, b.y));
    o.z = gelu_tanh(fmaf(a2, inv, b.z));
    o.w = gelu_tanh(fmaf(a3, inv, b.w));
    *reinterpret_cast<float4*>(&out[(size_t)w * D + j]) = o;
}

// ---------------------------------------------------------------------------
extern "C" void kernel_launch(void* const* d_in, const int* in_sizes, int n_in,
                              void* d_out, int out_size) {
    const float* x     = (const float*)d_in[0];
    const int*   edges = (const int*)d_in[1];
    const float* W     = (const float*)d_in[2]; // (D, H, U) row-major == D x 128
    const float* ka1   = (const float*)d_in[3];
    const float* battn = (const float*)d_in[4];
    const float* bias  = (const float*)d_in[5];
    float* out = (float*)d_out;

    const int n_nodes = in_sizes[0] / D;
    const int n_edges = in_sizes[1] / 2;
    const int nb = (n_nodes + SCAN_BLK - 1) / SCAN_BLK;

    // 1. zero degree histogram
    init_deg_kernel<<<(n_nodes + 255) / 256, 256>>>(n_nodes);
    // 2. projection GEMM (f32x2 packed)
    gemm_kernel<<<(n_nodes + 31) / 32, 128>>>(x, W, n_nodes);
    // 3. in-degree histogram
    hist_kernel<<<(n_edges + 255) / 256, 256>>>((const int2*)edges, n_edges);
    // 4. multi-block exclusive scan -> rowptr/cursor
    scan_local_kernel<<<nb, SCAN_BLK>>>(n_nodes);
    scan_blocksum_kernel<<<1, 32>>>(nb);
    scan_finalize_kernel<<<nb, SCAN_BLK>>>(n_nodes, n_edges);
    // 5. scatter sources into CSR
    scatter_kernel<<<(n_edges + 255) / 256, 256>>>((const int2*)edges, n_edges);
    // 6. fused per-node attention (score + softmax + aggregate + bias + gelu)
    {
        int threads = 256;
        int blocks = (n_nodes * 32 + threads - 1) / threads;
        attn_kernel<<<blocks, threads>>>(ka1, battn, bias, out, n_nodes);
    }
}